// round 14
// baseline (speedup 1.0000x reference)
#include <cuda_runtime.h>
#include <cstdint>

#define Bn 64
#define Tn 64
#define Dn 64
#define Pn 63
typedef unsigned long long ull;

// ---------------- device scratch ----------------
__device__ __align__(16) float g_emb[Tn * Bn * 128];         // [t][b][e]
__device__ __align__(16) ull   g_embP[Tn * 32 * 128];        // [t][rpg][e]
__device__ __align__(16) ull   g_giP[64 * 2 * 32 * 3 * 128]; // [t][gru][rpg][gate][k]
__device__ __align__(16) ull   g_xP[64 * 32 * 64];           // [j][bp][d]
__device__ __align__(16) float g_WiaT[128 * 384];            // [e][u]
__device__ __align__(16) float g_WibT[128 * 384];
// combined per-warp tiles: [w 8][tile 8][ Wh: li16 x 96 | Wb: li16 x 32 ] = 2048 floats (8KB)
__device__ __align__(16) float g_WC[8 * 8 * 2048];
__device__ __align__(16) float g_WembT[64 * 128];            // [d][e]
__device__ __align__(16) float g_WoWemb[128 * 64];           // [e][d]

// ---------------- f32x2 helpers ----------------
__device__ __forceinline__ ull pack2(float x, float y) {
    ull r; asm("mov.b64 %0, {%1,%2};" : "=l"(r) : "f"(x), "f"(y)); return r;
}
__device__ __forceinline__ float2 unpack2(ull v) {
    float2 r; asm("mov.b64 {%0,%1}, %2;" : "=f"(r.x), "=f"(r.y) : "l"(v)); return r;
}
__device__ __forceinline__ ull fma2(ull a, ull b, ull c) {
    ull d; asm("fma.rn.f32x2 %0, %1, %2, %3;" : "=l"(d) : "l"(a), "l"(b), "l"(c)); return d;
}
__device__ __forceinline__ ull mul2(ull a, ull b) {
    ull d; asm("mul.rn.f32x2 %0, %1, %2;" : "=l"(d) : "l"(a), "l"(b)); return d;
}
__device__ __forceinline__ ull add2(ull a, ull b) {
    ull d; asm("add.rn.f32x2 %0, %1, %2;" : "=l"(d) : "l"(a), "l"(b)); return d;
}
__device__ __forceinline__ float sigmoidf_(float v) {
    return __fdividef(1.f, 1.f + __expf(-v));
}
__device__ __forceinline__ float tanhfast(float v) {
    float e = __expf(2.f * v);
    return 1.f - __fdividef(2.f, e + 1.f);
}
__device__ __forceinline__ float gru_step(float ir, float iz, float in_,
                                          float hr, float hz, float hn, float h) {
    float r = sigmoidf_(ir + hr);
    float z = sigmoidf_(iz + hz);
    float n = tanhfast(in_ + r * hn);
    return n + z * (h - n);
}

// ---------------- cp.async helpers ----------------
__device__ __forceinline__ void cp16(uint32_t dst, const void* src) {
    asm volatile("cp.async.cg.shared.global [%0], [%1], 16;\n" :: "r"(dst), "l"(src));
}
__device__ __forceinline__ void cp_commit() {
    asm volatile("cp.async.commit_group;\n" ::: "memory");
}
__device__ __forceinline__ void cp_wait1() {
    asm volatile("cp.async.wait_group 1;\n" ::: "memory");
}
__device__ __forceinline__ void cp_wait0() {
    asm volatile("cp.async.wait_group 0;\n" ::: "memory");
}

// ---------------- prep ----------------
__global__ void prep_transpose(const float* __restrict__ x,
                               const float* __restrict__ Wh_a,
                               const float* __restrict__ Wh_b,
                               const float* __restrict__ Wi_a,
                               const float* __restrict__ Wi_b,
                               const float* __restrict__ Wb,
                               const float* __restrict__ W_emb,
                               const float* __restrict__ Wo) {
    int idx = blockIdx.x * blockDim.x + threadIdx.x;
    int stride = gridDim.x * blockDim.x;
    for (int n = idx; n < 128 * 384; n += stride) {
        int u = n % 384, i = n / 384;
        g_WiaT[n] = Wi_a[u * 128 + i];
        g_WibT[n] = Wi_b[u * 128 + i];
    }
    // Wh part of combined tiles
    for (int n = idx; n < 8 * 128 * 32; n += stride) {
        int w = n >> 12;
        int rem = n & 4095;
        int i = rem >> 5, kk = rem & 31;
        int gru = w >> 2, band = w & 3;
        int kq = band * 32 + kk;
        const float* Wh = gru ? Wh_b : Wh_a;
        float wr = Wh[kq * 128 + i];
        float wz = Wh[(128 + kq) * 128 + i];
        float wn = Wh[(256 + kq) * 128 + i];
        int tl = i >> 4, li = i & 15;
        int bas = (w * 8 + tl) * 2048 + li * 96;
        g_WC[bas + 2 * kk]     = wr;
        g_WC[bas + 2 * kk + 1] = wz;
        g_WC[bas + 64 + kk]    = wn;
    }
    // Wb part of combined tiles (duplicated across gru halves)
    for (int n = idx; n < 8 * 128 * 32; n += stride) {
        int w = n >> 12;
        int rem = n & 4095;
        int i = rem >> 5, kk = rem & 31;
        int band = w & 3;
        int tl = i >> 4, li = i & 15;
        g_WC[(w * 8 + tl) * 2048 + 1536 + li * 32 + kk] =
            Wb[(band * 32 + kk) * 128 + i];
    }
    for (int n = idx; n < 64 * 128; n += stride) {
        int e = n % 128, d = n / 128;
        g_WembT[n] = W_emb[e * 64 + d];
    }
    for (int n = idx; n < 128 * 64; n += stride) {
        int d = n % 64, e = n / 64;
        g_WoWemb[n] = Wo[e] * W_emb[e * 64 + d];
    }
    for (int n = idx; n < 64 * 32 * 64; n += stride) {
        int j = n >> 11;
        int bp = (n >> 6) & 31;
        int d = n & 63;
        float x0 = x[((size_t)(2 * bp) * Tn + j) * Dn + d];
        float x1 = x[((size_t)(2 * bp + 1) * Tn + j) * Dn + d];
        g_xP[n] = pack2(x0, x1);
    }
}

// ---------------- emb ----------------
__global__ void emb_kernel(const float* __restrict__ x, const float* __restrict__ b_emb) {
    __shared__ float xs[64];
    int tb = blockIdx.x;
    int t_ = tb >> 6, b = tb & 63;
    int e = threadIdx.x;
    if (e < 64) xs[e] = x[((size_t)b * Tn + t_) * Dn + e];
    __syncthreads();
    float acc = 0.f;
#pragma unroll 8
    for (int d = 0; d < 64; ++d) acc = fmaf(g_WembT[d * 128 + e], xs[d], acc);
    g_emb[(size_t)tb * 128 + e] = acc + b_emb[e];
}

// ---------------- gi (packed) + emb packing ----------------
__global__ void gi_kernel(const float* __restrict__ bi_a, const float* __restrict__ bi_b) {
    __shared__ float es[128];
    int tb = blockIdx.x;
    int t_ = tb >> 6, b = tb & 63;
    int t = threadIdx.x;
    if (t < 128) es[t] = g_emb[(size_t)tb * 128 + t];
    __syncthreads();
    float* gf = (float*)g_giP;
    for (int u = t; u < 768; u += 256) {
        const float* WT;
        const float* bi;
        int gru, uu;
        if (u < 384) { WT = g_WiaT; bi = bi_a; gru = 0; uu = u; }
        else         { WT = g_WibT; bi = bi_b; gru = 1; uu = u - 384; }
        float acc = 0.f;
#pragma unroll 8
        for (int e = 0; e < 128; ++e) acc = fmaf(WT[e * 384 + uu], es[e], acc);
        int gate = uu >> 7, k = uu & 127;
        size_t ullIdx = (((size_t)(t_ * 2 + gru) * 32 + (b >> 1)) * 3 + gate) * 128 + k;
        gf[ullIdx * 2 + (b & 1)] = acc + bi[uu];
    }
    if ((b & 1) == 0 && t < 128) {
        g_embP[((size_t)t_ * 32 + (b >> 1)) * 128 + t] =
            pack2(g_emb[(size_t)tb * 128 + t], g_emb[(size_t)(tb + 1) * 128 + t]);
    }
}

// ---------------- main persistent kernel ----------------
// 256 threads, 8 warps. Combined (Wh|Wb) tile rings; fused gh(s+1)+beta(s) loop;
// unnormalized softmax (|preA| <= ~3, exp-safe) -> only 2 barriers per step.
#define RING_OFF   0                  // 8 warps x 2 slots x 8192 = 131072
#define SHH_OFF    131072             // ull [2][2][128][8] = 32768
#define BETA_OFF   163840             // ull [8][128] = 8192
#define WOW_OFF    172032             // float [128][64] = 32768
#define SCAL_OFF   204800             // preA[16], l[16], Wa[128]
#define SMEM_TOTAL 205824

__global__ __launch_bounds__(256, 1) void retain_main(
    const float* __restrict__ bh_a, const float* __restrict__ bh_b,
    const float* __restrict__ Wa, const float* __restrict__ ba,
    const float* __restrict__ bb, const float* __restrict__ Wo,
    const float* __restrict__ bo, int nq, float* __restrict__ out) {

    extern __shared__ char dsm[];
    float* smw = (float*)dsm;
    ull (*sh_h)[2][128][8] = (ull (*)[2][128][8])(dsm + SHH_OFF);
    ull (*sh_betaP)[128]   = (ull (*)[128])(dsm + BETA_OFF);
    float* sWo             = (float*)(dsm + WOW_OFF);
    float* sh_preA  = (float*)(dsm + SCAL_OFF);    // [16]
    float* sh_l     = sh_preA + 16;                // [16]
    float* sh_Wa    = sh_preA + 32;                // [128]

    const int t = threadIdx.x;
    const int pb = blockIdx.x >> 2;
    const int chunkI = blockIdx.x & 3;
    const int b0 = chunkI * 16;

    const int w = t >> 5;
    const int lane = t & 31;
    const int gru = t >> 7;
    const int k = t & 127;
    const int kk = lane;
    const int q = t >> 6;

    const float* bh = gru ? bh_b : bh_a;
    const float bhr = bh[k], bhz = bh[128 + k], bhn = bh[256 + k];
    const float ba0 = ba[0], bbk = bb[k];
    const int base = Pn - nq;

    for (int n = t; n < 8192; n += 256) sWo[n] = g_WoWemb[n];
    if (t < 128) sh_Wa[t] = Wa[t];

    const bool seg2 = (pb < 31) && (pb >= base);
    const int totalSteps = (63 - pb) + (seg2 ? pb + 1 : 0);
    const int totalTiles = 8 * totalSteps;

    uint32_t ringB = (uint32_t)__cvta_generic_to_shared(dsm) + (uint32_t)(w * 16384);
    int issIdx = 0, issM = 0, issSlot = 0, consSlot = 0;

#define ISSUE_ONE() do {                                                        \
        if (issIdx < totalTiles) {                                              \
            const char* _src = (const char*)g_WC + ((size_t)(w * 8 + issM)) * 8192; \
            uint32_t _d = ringB + (uint32_t)(issSlot * 8192);                   \
            for (int _o = lane * 16; _o < 8192; _o += 512) cp16(_d + _o, _src + _o); \
            cp_commit();                                                        \
            ++issIdx; if (++issM == 8) issM = 0; issSlot ^= 1;                  \
        }                                                                       \
    } while (0)

#define WAITC() do {                                                            \
        if (issIdx < totalTiles) cp_wait1(); else cp_wait0();                   \
        __syncwarp();                                                           \
    } while (0)

    ISSUE_ONE();
    ISSUE_ONE();

    ull aR[8], aZ[8], aN[8];   // gh accumulators, pipelined across steps
    ull gbuf[24];              // gi for the current step

    for (int seg = 0; seg < 2; ++seg) {
        const int p = seg ? pb : 62 - pb;
        if (seg && !seg2) break;

        for (int n = t; n < 2 * 128 * 8; n += 256)
            ((ull*)sh_h[0])[n] = 0ull;
        ull cacc[4] = {0ull, 0ull, 0ull, 0ull};
        ull gacc[2] = {0ull, 0ull};
        ull lacc0 = 0ull, lacc1 = 0ull;   // l sums for pairs q and q+4
        // h(0)=0 -> gh(0)=0
#pragma unroll
        for (int r = 0; r < 8; ++r) { aR[r] = 0ull; aZ[r] = 0ull; aN[r] = 0ull; }
        // prefetch gi for step 0 (j = p)
        {
            const ull* gb = g_giP + (((size_t)(p * 2 + gru) * 32 + (b0 >> 1)) * 3) * 128 + k;
#pragma unroll
            for (int r = 0; r < 8; ++r) {
                gbuf[r * 3]     = gb[(size_t)r * 384];
                gbuf[r * 3 + 1] = gb[(size_t)r * 384 + 128];
                gbuf[r * 3 + 2] = gb[(size_t)r * 384 + 256];
            }
        }
        __syncthreads();

        for (int s = 0; s <= p; ++s) {
            const int j = p - s;
            const int cb = s & 1;
            const ull (*cur)[8]  = sh_h[cb][gru];
            ull (*nxtg)[8]       = sh_h[cb ^ 1][gru];
            const ull (*nxtA)[8] = sh_h[cb ^ 1][0];
            const ull (*nxtB)[8] = sh_h[cb ^ 1][1];

            // ---- phase 2: GRU update for 8 row-pairs at hidden k ----
            {
#pragma unroll
                for (int r = 0; r < 8; ++r) {
                    float2 gr = unpack2(gbuf[r * 3]);
                    float2 gz = unpack2(gbuf[r * 3 + 1]);
                    float2 gn = unpack2(gbuf[r * 3 + 2]);
                    float2 hr = unpack2(aR[r]);
                    float2 hz = unpack2(aZ[r]);
                    float2 hn = unpack2(aN[r]);
                    float2 ho = unpack2(cur[k][r]);
                    float hx = gru_step(gr.x, gz.x, gn.x,
                                        hr.x + bhr, hz.x + bhz, hn.x + bhn, ho.x);
                    float hy = gru_step(gr.y, gz.y, gn.y,
                                        hr.y + bhr, hz.y + bhz, hn.y + bhn, ho.y);
                    nxtg[k][r] = pack2(hx, hy);
                }
            }
            __syncthreads();   // BAR1: h(s+1) visible

            // ---- prefetch gi for step s+1 (covered by fused loop) ----
            {
                int jn = (j > 0) ? j - 1 : 0;
                const ull* gb = g_giP + (((size_t)(jn * 2 + gru) * 32 + (b0 >> 1)) * 3) * 128 + k;
#pragma unroll
                for (int r = 0; r < 8; ++r) {
                    gbuf[r * 3]     = gb[(size_t)r * 384];
                    gbuf[r * 3 + 1] = gb[(size_t)r * 384 + 128];
                    gbuf[r * 3 + 2] = gb[(size_t)r * 384 + 256];
                }
            }

            // ---- preA(s) on the new h ----
            {
#pragma unroll
                for (int rr = 0; rr < 2; ++rr) {
                    int r = w + 8 * rr;
                    float part = 0.f;
#pragma unroll
                    for (int ii = 0; ii < 4; ++ii) {
                        int i = lane + 32 * ii;
                        float2 hv = unpack2(nxtA[i][r >> 1]);
                        part = fmaf(sh_Wa[i], (r & 1) ? hv.y : hv.x, part);
                    }
#pragma unroll
                    for (int o = 16; o; o >>= 1)
                        part += __shfl_xor_sync(0xffffffffu, part, o);
                    if (lane == 0) sh_preA[r] = fmaf(0.5f, part, ba0);
                }
            }

            // ---- FUSED: gh(s+1) (24 fma2) + beta(s) (4 fma2) over i = 0..127 ----
#pragma unroll
            for (int r = 0; r < 8; ++r) { aR[r] = 0ull; aZ[r] = 0ull; aN[r] = 0ull; }
            ull bacc[4] = {0ull, 0ull, 0ull, 0ull};
#pragma unroll 1
            for (int tl = 0; tl < 8; ++tl) {
                WAITC();
                const float* wp = smw + w * 4096 + consSlot * 2048;
                consSlot ^= 1;
                const ull (*hrow)[8]  = (const ull (*)[8])&nxtg[tl * 16]; // my gru h(s+1)
                const ull (*hrowB)[8] = &nxtB[tl * 16];                   // GRU-b h(s+1)
#pragma unroll
                for (int li = 0; li < 16; ++li) {
                    float2 rz = *(const float2*)(wp + li * 96 + 2 * kk);
                    float wnv = wp[li * 96 + 64 + kk];
                    float wbv = wp[1536 + li * 32 + kk];
                    ull wr2 = pack2(rz.x, rz.x), wz2 = pack2(rz.y, rz.y);
                    ull wn2 = pack2(wnv, wnv), wb2 = pack2(wbv, wbv);
                    const ulonglong2* hp = reinterpret_cast<const ulonglong2*>(hrow[li]);
                    ulonglong2 hA = hp[0], hB = hp[1], hC = hp[2], hD = hp[3];
                    ulonglong2 b0v, b1v;
                    if (gru) {           // my beta rows are my own hC/hD (warp-uniform branch)
                        b0v = hC; b1v = hD;
                    } else {
                        const ulonglong2* hq =
                            reinterpret_cast<const ulonglong2*>(hrowB[li]);
                        b0v = hq[0]; b1v = hq[1];
                    }
                    aR[0] = fma2(wr2, hA.x, aR[0]); aZ[0] = fma2(wz2, hA.x, aZ[0]); aN[0] = fma2(wn2, hA.x, aN[0]);
                    bacc[0] = fma2(wb2, b0v.x, bacc[0]);
                    aR[1] = fma2(wr2, hA.y, aR[1]); aZ[1] = fma2(wz2, hA.y, aZ[1]); aN[1] = fma2(wn2, hA.y, aN[1]);
                    bacc[1] = fma2(wb2, b0v.y, bacc[1]);
                    aR[2] = fma2(wr2, hB.x, aR[2]); aZ[2] = fma2(wz2, hB.x, aZ[2]); aN[2] = fma2(wn2, hB.x, aN[2]);
                    bacc[2] = fma2(wb2, b1v.x, bacc[2]);
                    aR[3] = fma2(wr2, hB.y, aR[3]); aZ[3] = fma2(wz2, hB.y, aZ[3]); aN[3] = fma2(wn2, hB.y, aN[3]);
                    bacc[3] = fma2(wb2, b1v.y, bacc[3]);
                    aR[4] = fma2(wr2, hC.x, aR[4]); aZ[4] = fma2(wz2, hC.x, aZ[4]); aN[4] = fma2(wn2, hC.x, aN[4]);
                    aR[5] = fma2(wr2, hC.y, aR[5]); aZ[5] = fma2(wz2, hC.y, aZ[5]); aN[5] = fma2(wn2, hC.y, aN[5]);
                    aR[6] = fma2(wr2, hD.x, aR[6]); aZ[6] = fma2(wz2, hD.x, aZ[6]); aN[6] = fma2(wn2, hD.x, aN[6]);
                    aR[7] = fma2(wr2, hD.y, aR[7]); aZ[7] = fma2(wz2, hD.y, aZ[7]); aN[7] = fma2(wn2, hD.y, aN[7]);
                }
                ISSUE_ONE();
            }

            ull bt[4];
#pragma unroll
            for (int c = 0; c < 4; ++c) {
                float2 v = unpack2(bacc[c]);
                bt[c] = pack2(tanhfast(fmaf(0.5f, v.x, bbk)),
                              tanhfast(fmaf(0.5f, v.y, bbk)));
                sh_betaP[4 * gru + c][k] = bt[c];
            }
            __syncthreads();   // BAR2: betaP + preA visible

            // ---- per-thread softmax weights (no max-sub; |preA| <= ~3) ----
            ull wcv[4], wg0, wg1;
            {
#pragma unroll
                for (int c = 0; c < 4; ++c) {
                    int rp = 4 * gru + c;
                    wcv[c] = pack2(__expf(sh_preA[2 * rp]), __expf(sh_preA[2 * rp + 1]));
                }
                wg0 = pack2(__expf(sh_preA[2 * q]), __expf(sh_preA[2 * q + 1]));
                wg1 = pack2(__expf(sh_preA[2 * q + 8]), __expf(sh_preA[2 * q + 9]));
                lacc0 = add2(lacc0, wg0);
                lacc1 = add2(lacc1, wg1);
            }

            // ---- prefetch embP/xP for 3c (covered by e_chain) ----
            ull ebr[4], xr0, xr1;
            {
                const ull* ebp = g_embP + ((size_t)j * 32 + (b0 >> 1) + 4 * gru) * 128 + k;
#pragma unroll
                for (int c = 0; c < 4; ++c) ebr[c] = ebp[(size_t)c * 128];
                const ull* xb = g_xP + ((size_t)j * 32 + (b0 >> 1) + q) * 64 + (t & 63);
                xr0 = xb[0];
                xr1 = xb[4 * 64];
            }

            // ---- e_chain ----
            ull ea0 = 0ull, ea1 = 0ull;
            {
                const ull* bp0 = sh_betaP[q];
                const ull* bp1 = sh_betaP[q + 4];
                const float* wcp = sWo + (t & 63);
#pragma unroll 4
                for (int e = 0; e < 128; ++e) {
                    float wc = wcp[e * 64];
                    ull wc2 = pack2(wc, wc);
                    ea0 = fma2(wc2, bp0[e], ea0);
                    ea1 = fma2(wc2, bp1[e], ea1);
                }
            }

            // ---- accumulators (unnormalized; registers only) ----
            {
#pragma unroll
                for (int c = 0; c < 4; ++c)
                    cacc[c] = fma2(mul2(wcv[c], bt[c]), ebr[c], cacc[c]);
                gacc[0] = fma2(mul2(wg0, ea0), xr0, gacc[0]);
                gacc[1] = fma2(mul2(wg1, ea1), xr1, gacc[1]);
            }
            // no BAR3: next step's writes to shared state are all fenced by
            // BAR1(s+1) (sh_betaP/preA) or are same-thread (sh_h ping-pong).
        } // steps

        // ---- finalize ----
        __syncthreads();
        if (p >= base) {
            const int qi = p - base;
#pragma unroll
            for (int c = 0; c < 4; ++c) sh_betaP[4 * gru + c][k] = cacc[c];
            if ((t & 63) == 0) {          // one writer per quarter: rows 2q,2q+1,2q+8,2q+9
                float2 l0 = unpack2(lacc0), l1 = unpack2(lacc1);
                sh_l[2 * q] = l0.x; sh_l[2 * q + 1] = l0.y;
                sh_l[2 * q + 8] = l1.x; sh_l[2 * q + 9] = l1.y;
            }
            __syncthreads();

            if (t < 16) {
                float sum = 0.f;
                const ull* Crow = sh_betaP[t >> 1];
                const bool hi = (t & 1);
#pragma unroll 8
                for (int e = 0; e < 128; ++e) {
                    float2 v = unpack2(Crow[e]);
                    sum = fmaf(Wo[e], hi ? v.y : v.x, sum);
                }
                out[(size_t)(b0 + t) * nq + qi] = __fdividef(sum, sh_l[t]) + bo[0];
            }
            {
                float inv = __fdividef(1.f, (float)(p + 1));
                size_t wbase = (size_t)64 * nq;
                float2 lg0 = unpack2(lacc0), lg1 = unpack2(lacc1);
#pragma unroll
                for (int cc = 0; cc < 2; ++cc) {
                    int rp = q + 4 * cc;
                    float2 gv = unpack2(gacc[cc]);
                    float lx = cc ? lg1.x : lg0.x;
                    float ly = cc ? lg1.y : lg0.y;
                    out[wbase + ((size_t)(b0 + 2 * rp) * nq + qi) * 64 + (t & 63)] =
                        __fdividef(gv.x, lx) * inv;
                    out[wbase + ((size_t)(b0 + 2 * rp + 1) * nq + qi) * 64 + (t & 63)] =
                        __fdividef(gv.y, ly) * inv;
                }
            }
        }
        __syncthreads();
    } // segments
#undef WAITC
#undef ISSUE_ONE
}

// ---------------- launch ----------------
extern "C" void kernel_launch(void* const* d_in, const int* in_sizes, int n_in,
                              void* d_out, int out_size) {
    const float* x     = (const float*)d_in[0];
    const float* W_emb = (const float*)d_in[1];
    const float* b_emb = (const float*)d_in[2];
    const float* Wi_a  = (const float*)d_in[3];
    const float* Wh_a  = (const float*)d_in[4];
    const float* bi_a  = (const float*)d_in[5];
    const float* bh_a  = (const float*)d_in[6];
    const float* Wi_b  = (const float*)d_in[7];
    const float* Wh_b  = (const float*)d_in[8];
    const float* bi_b  = (const float*)d_in[9];
    const float* bh_b  = (const float*)d_in[10];
    const float* Wa    = (const float*)d_in[11];
    const float* ba    = (const float*)d_in[12];
    const float* Wb    = (const float*)d_in[13];
    const float* bb    = (const float*)d_in[14];
    const float* Wo    = (const float*)d_in[15];
    const float* bo    = (const float*)d_in[16];
    float* out = (float*)d_out;

    int nq = out_size / (64 * 65);

    static int smem_set = 0;
    if (!smem_set) {
        cudaFuncSetAttribute(retain_main,
                             cudaFuncAttributeMaxDynamicSharedMemorySize, SMEM_TOTAL);
        smem_set = 1;
    }

    prep_transpose<<<256, 256>>>(x, Wh_a, Wh_b, Wi_a, Wi_b, Wb, W_emb, Wo);
    emb_kernel<<<Tn * Bn, 128>>>(x, b_emb);
    gi_kernel<<<Tn * Bn, 256>>>(bi_a, bi_b);
    retain_main<<<128, 256, SMEM_TOTAL>>>(bh_a, bh_b, Wa, ba, bb, Wo, bo, nq, out);
}

// round 15
// speedup vs baseline: 1.0611x; 1.0611x over previous
#include <cuda_runtime.h>
#include <cstdint>

#define Bn 64
#define Tn 64
#define Dn 64
#define Pn 63
typedef unsigned long long ull;

// ---------------- device scratch ----------------
__device__ __align__(16) float g_emb[Tn * Bn * 128];         // [t][b][e]
__device__ __align__(16) ull   g_embP[Tn * 32 * 128];        // [t][rpg][e]
__device__ __align__(16) ull   g_giP[64 * 2 * 32 * 3 * 128]; // [t][gru][rpg][gate][k]
__device__ __align__(16) ull   g_xP[64 * 32 * 64];           // [j][bp][d]
__device__ __align__(16) float g_WiaT[128 * 384];            // [e][u]
__device__ __align__(16) float g_WibT[128 * 384];
// combined per-warp tiles: [w 8][tile 8][ Wh: li16 x 96 | Wb: li16 x 32 ] = 2048 floats (8KB)
__device__ __align__(16) float g_WC[8 * 8 * 2048];
__device__ __align__(16) float g_WembT[64 * 128];            // [d][e]
__device__ __align__(16) float g_WoWemb[128 * 64];           // [e][d]

// ---------------- f32x2 helpers ----------------
__device__ __forceinline__ ull pack2(float x, float y) {
    ull r; asm("mov.b64 %0, {%1,%2};" : "=l"(r) : "f"(x), "f"(y)); return r;
}
__device__ __forceinline__ float2 unpack2(ull v) {
    float2 r; asm("mov.b64 {%0,%1}, %2;" : "=f"(r.x), "=f"(r.y) : "l"(v)); return r;
}
__device__ __forceinline__ ull fma2(ull a, ull b, ull c) {
    ull d; asm("fma.rn.f32x2 %0, %1, %2, %3;" : "=l"(d) : "l"(a), "l"(b), "l"(c)); return d;
}
__device__ __forceinline__ ull mul2(ull a, ull b) {
    ull d; asm("mul.rn.f32x2 %0, %1, %2;" : "=l"(d) : "l"(a), "l"(b)); return d;
}
__device__ __forceinline__ ull add2(ull a, ull b) {
    ull d; asm("add.rn.f32x2 %0, %1, %2;" : "=l"(d) : "l"(a), "l"(b)); return d;
}
__device__ __forceinline__ float sigmoidf_(float v) {
    return __fdividef(1.f, 1.f + __expf(-v));
}
__device__ __forceinline__ float tanhfast(float v) {
    float e = __expf(2.f * v);
    return 1.f - __fdividef(2.f, e + 1.f);
}
__device__ __forceinline__ float gru_step(float ir, float iz, float in_,
                                          float hr, float hz, float hn, float h) {
    float r = sigmoidf_(ir + hr);
    float z = sigmoidf_(iz + hz);
    float n = tanhfast(in_ + r * hn);
    return n + z * (h - n);
}

// ---------------- cp.async helpers ----------------
__device__ __forceinline__ void cp16(uint32_t dst, const void* src) {
    asm volatile("cp.async.cg.shared.global [%0], [%1], 16;\n" :: "r"(dst), "l"(src));
}
__device__ __forceinline__ void cp_commit() {
    asm volatile("cp.async.commit_group;\n" ::: "memory");
}
__device__ __forceinline__ void cp_wait1() {
    asm volatile("cp.async.wait_group 1;\n" ::: "memory");
}
__device__ __forceinline__ void cp_wait0() {
    asm volatile("cp.async.wait_group 0;\n" ::: "memory");
}

// ---------------- prep ----------------
__global__ void prep_transpose(const float* __restrict__ x,
                               const float* __restrict__ Wh_a,
                               const float* __restrict__ Wh_b,
                               const float* __restrict__ Wi_a,
                               const float* __restrict__ Wi_b,
                               const float* __restrict__ Wb,
                               const float* __restrict__ W_emb,
                               const float* __restrict__ Wo) {
    int idx = blockIdx.x * blockDim.x + threadIdx.x;
    int stride = gridDim.x * blockDim.x;
    for (int n = idx; n < 128 * 384; n += stride) {
        int u = n % 384, i = n / 384;
        g_WiaT[n] = Wi_a[u * 128 + i];
        g_WibT[n] = Wi_b[u * 128 + i];
    }
    // Wh part of combined tiles
    for (int n = idx; n < 8 * 128 * 32; n += stride) {
        int w = n >> 12;
        int rem = n & 4095;
        int i = rem >> 5, kk = rem & 31;
        int gru = w >> 2, band = w & 3;
        int kq = band * 32 + kk;
        const float* Wh = gru ? Wh_b : Wh_a;
        float wr = Wh[kq * 128 + i];
        float wz = Wh[(128 + kq) * 128 + i];
        float wn = Wh[(256 + kq) * 128 + i];
        int tl = i >> 4, li = i & 15;
        int bas = (w * 8 + tl) * 2048 + li * 96;
        g_WC[bas + 2 * kk]     = wr;
        g_WC[bas + 2 * kk + 1] = wz;
        g_WC[bas + 64 + kk]    = wn;
    }
    // Wb part of combined tiles (duplicated across gru halves)
    for (int n = idx; n < 8 * 128 * 32; n += stride) {
        int w = n >> 12;
        int rem = n & 4095;
        int i = rem >> 5, kk = rem & 31;
        int band = w & 3;
        int tl = i >> 4, li = i & 15;
        g_WC[(w * 8 + tl) * 2048 + 1536 + li * 32 + kk] =
            Wb[(band * 32 + kk) * 128 + i];
    }
    for (int n = idx; n < 64 * 128; n += stride) {
        int e = n % 128, d = n / 128;
        g_WembT[n] = W_emb[e * 64 + d];
    }
    for (int n = idx; n < 128 * 64; n += stride) {
        int d = n % 64, e = n / 64;
        g_WoWemb[n] = Wo[e] * W_emb[e * 64 + d];
    }
    for (int n = idx; n < 64 * 32 * 64; n += stride) {
        int j = n >> 11;
        int bp = (n >> 6) & 31;
        int d = n & 63;
        float x0 = x[((size_t)(2 * bp) * Tn + j) * Dn + d];
        float x1 = x[((size_t)(2 * bp + 1) * Tn + j) * Dn + d];
        g_xP[n] = pack2(x0, x1);
    }
}

// ---------------- emb ----------------
__global__ void emb_kernel(const float* __restrict__ x, const float* __restrict__ b_emb) {
    __shared__ float xs[64];
    int tb = blockIdx.x;
    int t_ = tb >> 6, b = tb & 63;
    int e = threadIdx.x;
    if (e < 64) xs[e] = x[((size_t)b * Tn + t_) * Dn + e];
    __syncthreads();
    float acc = 0.f;
#pragma unroll 8
    for (int d = 0; d < 64; ++d) acc = fmaf(g_WembT[d * 128 + e], xs[d], acc);
    g_emb[(size_t)tb * 128 + e] = acc + b_emb[e];
}

// ---------------- gi (packed) + emb packing ----------------
__global__ void gi_kernel(const float* __restrict__ bi_a, const float* __restrict__ bi_b) {
    __shared__ float es[128];
    int tb = blockIdx.x;
    int t_ = tb >> 6, b = tb & 63;
    int t = threadIdx.x;
    if (t < 128) es[t] = g_emb[(size_t)tb * 128 + t];
    __syncthreads();
    float* gf = (float*)g_giP;
    for (int u = t; u < 768; u += 256) {
        const float* WT;
        const float* bi;
        int gru, uu;
        if (u < 384) { WT = g_WiaT; bi = bi_a; gru = 0; uu = u; }
        else         { WT = g_WibT; bi = bi_b; gru = 1; uu = u - 384; }
        float acc = 0.f;
#pragma unroll 8
        for (int e = 0; e < 128; ++e) acc = fmaf(WT[e * 384 + uu], es[e], acc);
        int gate = uu >> 7, k = uu & 127;
        size_t ullIdx = (((size_t)(t_ * 2 + gru) * 32 + (b >> 1)) * 3 + gate) * 128 + k;
        gf[ullIdx * 2 + (b & 1)] = acc + bi[uu];
    }
    if ((b & 1) == 0 && t < 128) {
        g_embP[((size_t)t_ * 32 + (b >> 1)) * 128 + t] =
            pack2(g_emb[(size_t)tb * 128 + t], g_emb[(size_t)(tb + 1) * 128 + t]);
    }
}

// ---------------- main persistent kernel ----------------
// 256 threads, 8 warps. Combined (Wh|Wb) tile rings; fused gh(s+1)+beta(s) loop
// (identical to R13 inner loop); unnormalized softmax -> 2 barriers per step.
#define RING_OFF   0                  // 8 warps x 2 slots x 8192 = 131072
#define SHH_OFF    131072             // ull [2][2][128][8] = 32768
#define BETA_OFF   163840             // ull [8][128] = 8192
#define WOW_OFF    172032             // float [128][64] = 32768
#define SCAL_OFF   204800             // preA[16], l[16], Wa[128]
#define SMEM_TOTAL 205824

__global__ __launch_bounds__(256, 1) void retain_main(
    const float* __restrict__ bh_a, const float* __restrict__ bh_b,
    const float* __restrict__ Wa, const float* __restrict__ ba,
    const float* __restrict__ bb, const float* __restrict__ Wo,
    const float* __restrict__ bo, int nq, float* __restrict__ out) {

    extern __shared__ char dsm[];
    float* smw = (float*)dsm;
    ull (*sh_h)[2][128][8] = (ull (*)[2][128][8])(dsm + SHH_OFF);
    ull (*sh_betaP)[128]   = (ull (*)[128])(dsm + BETA_OFF);
    float* sWo             = (float*)(dsm + WOW_OFF);
    float* sh_preA  = (float*)(dsm + SCAL_OFF);    // [16]
    float* sh_l     = sh_preA + 16;                // [16]
    float* sh_Wa    = sh_preA + 32;                // [128]

    const int t = threadIdx.x;
    const int pb = blockIdx.x >> 2;
    const int chunkI = blockIdx.x & 3;
    const int b0 = chunkI * 16;

    const int w = t >> 5;
    const int lane = t & 31;
    const int gru = t >> 7;
    const int k = t & 127;
    const int kk = lane;
    const int q = t >> 6;

    const float* bh = gru ? bh_b : bh_a;
    const float bhr = bh[k], bhz = bh[128 + k], bhn = bh[256 + k];
    const float ba0 = ba[0], bbk = bb[k];
    const int base = Pn - nq;

    for (int n = t; n < 8192; n += 256) sWo[n] = g_WoWemb[n];
    if (t < 128) sh_Wa[t] = Wa[t];

    const bool seg2 = (pb < 31) && (pb >= base);
    const int totalSteps = (63 - pb) + (seg2 ? pb + 1 : 0);
    const int totalTiles = 8 * totalSteps;

    uint32_t ringB = (uint32_t)__cvta_generic_to_shared(dsm) + (uint32_t)(w * 16384);
    int issIdx = 0, issM = 0, issSlot = 0, consSlot = 0;

#define ISSUE_ONE() do {                                                        \
        if (issIdx < totalTiles) {                                              \
            const char* _src = (const char*)g_WC + ((size_t)(w * 8 + issM)) * 8192; \
            uint32_t _d = ringB + (uint32_t)(issSlot * 8192);                   \
            for (int _o = lane * 16; _o < 8192; _o += 512) cp16(_d + _o, _src + _o); \
            cp_commit();                                                        \
            ++issIdx; if (++issM == 8) issM = 0; issSlot ^= 1;                  \
        }                                                                       \
    } while (0)

#define WAITC() do {                                                            \
        if (issIdx < totalTiles) cp_wait1(); else cp_wait0();                   \
        __syncwarp();                                                           \
    } while (0)

    ISSUE_ONE();
    ISSUE_ONE();

    ull aR[8], aZ[8], aN[8];   // gh accumulators, pipelined across steps
    ull gbuf[24];              // gi for the current step

    for (int seg = 0; seg < 2; ++seg) {
        const int p = seg ? pb : 62 - pb;
        if (seg && !seg2) break;

        for (int n = t; n < 2 * 128 * 8; n += 256)
            ((ull*)sh_h[0])[n] = 0ull;
        ull cacc[4] = {0ull, 0ull, 0ull, 0ull};
        ull gacc[2] = {0ull, 0ull};
        ull lacc0 = 0ull, lacc1 = 0ull;
        // h(0)=0 -> gh(0)=0
#pragma unroll
        for (int r = 0; r < 8; ++r) { aR[r] = 0ull; aZ[r] = 0ull; aN[r] = 0ull; }
        // prefetch gi for step 0 (j = p)
        {
            const ull* gb = g_giP + (((size_t)(p * 2 + gru) * 32 + (b0 >> 1)) * 3) * 128 + k;
#pragma unroll
            for (int r = 0; r < 8; ++r) {
                gbuf[r * 3]     = gb[(size_t)r * 384];
                gbuf[r * 3 + 1] = gb[(size_t)r * 384 + 128];
                gbuf[r * 3 + 2] = gb[(size_t)r * 384 + 256];
            }
        }
        __syncthreads();

        for (int s = 0; s <= p; ++s) {
            const int j = p - s;
            const int cb = s & 1;
            const ull (*cur)[8]  = sh_h[cb][gru];
            ull (*nxtg)[8]       = sh_h[cb ^ 1][gru];
            const ull (*nxtA)[8] = sh_h[cb ^ 1][0];
            const ull (*nxtB)[8] = sh_h[cb ^ 1][1];

            // ---- phase 2: GRU update for 8 row-pairs at hidden k ----
            {
#pragma unroll
                for (int r = 0; r < 8; ++r) {
                    float2 gr = unpack2(gbuf[r * 3]);
                    float2 gz = unpack2(gbuf[r * 3 + 1]);
                    float2 gn = unpack2(gbuf[r * 3 + 2]);
                    float2 hr = unpack2(aR[r]);
                    float2 hz = unpack2(aZ[r]);
                    float2 hn = unpack2(aN[r]);
                    float2 ho = unpack2(cur[k][r]);
                    float hx = gru_step(gr.x, gz.x, gn.x,
                                        hr.x + bhr, hz.x + bhz, hn.x + bhn, ho.x);
                    float hy = gru_step(gr.y, gz.y, gn.y,
                                        hr.y + bhr, hz.y + bhz, hn.y + bhn, ho.y);
                    nxtg[k][r] = pack2(hx, hy);
                }
            }
            __syncthreads();   // BAR1: h(s+1) visible

            // ---- prefetch gi for step s+1 (covered by fused loop) ----
            {
                int jn = (j > 0) ? j - 1 : 0;
                const ull* gb = g_giP + (((size_t)(jn * 2 + gru) * 32 + (b0 >> 1)) * 3) * 128 + k;
#pragma unroll
                for (int r = 0; r < 8; ++r) {
                    gbuf[r * 3]     = gb[(size_t)r * 384];
                    gbuf[r * 3 + 1] = gb[(size_t)r * 384 + 128];
                    gbuf[r * 3 + 2] = gb[(size_t)r * 384 + 256];
                }
            }

            // ---- preA(s) on the new h ----
            {
#pragma unroll
                for (int rr = 0; rr < 2; ++rr) {
                    int r = w + 8 * rr;
                    float part = 0.f;
#pragma unroll
                    for (int ii = 0; ii < 4; ++ii) {
                        int i = lane + 32 * ii;
                        float2 hv = unpack2(nxtA[i][r >> 1]);
                        part = fmaf(sh_Wa[i], (r & 1) ? hv.y : hv.x, part);
                    }
#pragma unroll
                    for (int o = 16; o; o >>= 1)
                        part += __shfl_xor_sync(0xffffffffu, part, o);
                    if (lane == 0) sh_preA[r] = fmaf(0.5f, part, ba0);
                }
            }

            // ---- FUSED: gh(s+1) (24 fma2) + beta(s) (4 fma2) over i = 0..127 ----
#pragma unroll
            for (int r = 0; r < 8; ++r) { aR[r] = 0ull; aZ[r] = 0ull; aN[r] = 0ull; }
            ull bacc[4] = {0ull, 0ull, 0ull, 0ull};
#pragma unroll 1
            for (int tl = 0; tl < 8; ++tl) {
                WAITC();
                const float* wp = smw + w * 4096 + consSlot * 2048;
                consSlot ^= 1;
                const ull (*hrow)[8]  = (const ull (*)[8])&nxtg[tl * 16]; // my gru h(s+1)
                const ull (*hrowB)[8] = &nxtB[tl * 16];                   // GRU-b h(s+1)
#pragma unroll
                for (int li = 0; li < 16; ++li) {
                    float2 rz = *(const float2*)(wp + li * 96 + 2 * kk);
                    float wnv = wp[li * 96 + 64 + kk];
                    float wbv = wp[1536 + li * 32 + kk];
                    ull wr2 = pack2(rz.x, rz.x), wz2 = pack2(rz.y, rz.y);
                    ull wn2 = pack2(wnv, wnv), wb2 = pack2(wbv, wbv);
                    const ulonglong2* hp = reinterpret_cast<const ulonglong2*>(hrow[li]);
                    ulonglong2 hA = hp[0], hB = hp[1], hC = hp[2], hD = hp[3];
                    const ulonglong2* hq =
                        reinterpret_cast<const ulonglong2*>(hrowB[li] + 4 * gru);
                    ulonglong2 b0v = hq[0], b1v = hq[1];
                    aR[0] = fma2(wr2, hA.x, aR[0]); aZ[0] = fma2(wz2, hA.x, aZ[0]); aN[0] = fma2(wn2, hA.x, aN[0]);
                    bacc[0] = fma2(wb2, b0v.x, bacc[0]);
                    aR[1] = fma2(wr2, hA.y, aR[1]); aZ[1] = fma2(wz2, hA.y, aZ[1]); aN[1] = fma2(wn2, hA.y, aN[1]);
                    bacc[1] = fma2(wb2, b0v.y, bacc[1]);
                    aR[2] = fma2(wr2, hB.x, aR[2]); aZ[2] = fma2(wz2, hB.x, aZ[2]); aN[2] = fma2(wn2, hB.x, aN[2]);
                    bacc[2] = fma2(wb2, b1v.x, bacc[2]);
                    aR[3] = fma2(wr2, hB.y, aR[3]); aZ[3] = fma2(wz2, hB.y, aZ[3]); aN[3] = fma2(wn2, hB.y, aN[3]);
                    bacc[3] = fma2(wb2, b1v.y, bacc[3]);
                    aR[4] = fma2(wr2, hC.x, aR[4]); aZ[4] = fma2(wz2, hC.x, aZ[4]); aN[4] = fma2(wn2, hC.x, aN[4]);
                    aR[5] = fma2(wr2, hC.y, aR[5]); aZ[5] = fma2(wz2, hC.y, aZ[5]); aN[5] = fma2(wn2, hC.y, aN[5]);
                    aR[6] = fma2(wr2, hD.x, aR[6]); aZ[6] = fma2(wz2, hD.x, aZ[6]); aN[6] = fma2(wn2, hD.x, aN[6]);
                    aR[7] = fma2(wr2, hD.y, aR[7]); aZ[7] = fma2(wz2, hD.y, aZ[7]); aN[7] = fma2(wn2, hD.y, aN[7]);
                }
                ISSUE_ONE();
            }

            ull bt[4];
#pragma unroll
            for (int c = 0; c < 4; ++c) {
                float2 v = unpack2(bacc[c]);
                bt[c] = pack2(tanhfast(fmaf(0.5f, v.x, bbk)),
                              tanhfast(fmaf(0.5f, v.y, bbk)));
                sh_betaP[4 * gru + c][k] = bt[c];
            }
            __syncthreads();   // BAR2: betaP + preA visible

            // ---- per-thread softmax weights (no max-sub; |preA| <= ~3) ----
            ull wcv[4], wg0, wg1;
            {
#pragma unroll
                for (int c = 0; c < 4; ++c) {
                    int rp = 4 * gru + c;
                    wcv[c] = pack2(__expf(sh_preA[2 * rp]), __expf(sh_preA[2 * rp + 1]));
                }
                wg0 = pack2(__expf(sh_preA[2 * q]), __expf(sh_preA[2 * q + 1]));
                wg1 = pack2(__expf(sh_preA[2 * q + 8]), __expf(sh_preA[2 * q + 9]));
                lacc0 = add2(lacc0, wg0);
                lacc1 = add2(lacc1, wg1);
            }

            // ---- prefetch embP/xP for 3c (covered by e_chain) ----
            ull ebr[4], xr0, xr1;
            {
                const ull* ebp = g_embP + ((size_t)j * 32 + (b0 >> 1) + 4 * gru) * 128 + k;
#pragma unroll
                for (int c = 0; c < 4; ++c) ebr[c] = ebp[(size_t)c * 128];
                const ull* xb = g_xP + ((size_t)j * 32 + (b0 >> 1) + q) * 64 + (t & 63);
                xr0 = xb[0];
                xr1 = xb[4 * 64];
            }

            // ---- e_chain ----
            ull ea0 = 0ull, ea1 = 0ull;
            {
                const ull* bp0 = sh_betaP[q];
                const ull* bp1 = sh_betaP[q + 4];
                const float* wcp = sWo + (t & 63);
#pragma unroll 4
                for (int e = 0; e < 128; ++e) {
                    float wc = wcp[e * 64];
                    ull wc2 = pack2(wc, wc);
                    ea0 = fma2(wc2, bp0[e], ea0);
                    ea1 = fma2(wc2, bp1[e], ea1);
                }
            }

            // ---- accumulators (unnormalized; registers only) ----
            {
#pragma unroll
                for (int c = 0; c < 4; ++c)
                    cacc[c] = fma2(mul2(wcv[c], bt[c]), ebr[c], cacc[c]);
                gacc[0] = fma2(mul2(wg0, ea0), xr0, gacc[0]);
                gacc[1] = fma2(mul2(wg1, ea1), xr1, gacc[1]);
            }
            // no BAR3: next step's shared writes are fenced by BAR1(s+1) or same-thread.
        } // steps

        // ---- finalize ----
        __syncthreads();
        if (p >= base) {
            const int qi = p - base;
#pragma unroll
            for (int c = 0; c < 4; ++c) sh_betaP[4 * gru + c][k] = cacc[c];
            if ((t & 63) == 0) {          // one writer per quarter
                float2 l0 = unpack2(lacc0), l1 = unpack2(lacc1);
                sh_l[2 * q] = l0.x; sh_l[2 * q + 1] = l0.y;
                sh_l[2 * q + 8] = l1.x; sh_l[2 * q + 9] = l1.y;
            }
            __syncthreads();

            if (t < 16) {
                float sum = 0.f;
                const ull* Crow = sh_betaP[t >> 1];
                const bool hi = (t & 1);
#pragma unroll 8
                for (int e = 0; e < 128; ++e) {
                    float2 v = unpack2(Crow[e]);
                    sum = fmaf(Wo[e], hi ? v.y : v.x, sum);
                }
                out[(size_t)(b0 + t) * nq + qi] = __fdividef(sum, sh_l[t]) + bo[0];
            }
            {
                float inv = __fdividef(1.f, (float)(p + 1));
                size_t wbase = (size_t)64 * nq;
                float2 lg0 = unpack2(lacc0), lg1 = unpack2(lacc1);
#pragma unroll
                for (int cc = 0; cc < 2; ++cc) {
                    int rp = q + 4 * cc;
                    float2 gv = unpack2(gacc[cc]);
                    float lx = cc ? lg1.x : lg0.x;
                    float ly = cc ? lg1.y : lg0.y;
                    out[wbase + ((size_t)(b0 + 2 * rp) * nq + qi) * 64 + (t & 63)] =
                        __fdividef(gv.x, lx) * inv;
                    out[wbase + ((size_t)(b0 + 2 * rp + 1) * nq + qi) * 64 + (t & 63)] =
                        __fdividef(gv.y, ly) * inv;
                }
            }
        }
        __syncthreads();
    } // segments
#undef WAITC
#undef ISSUE_ONE
}

// ---------------- launch ----------------
extern "C" void kernel_launch(void* const* d_in, const int* in_sizes, int n_in,
                              void* d_out, int out_size) {
    const float* x     = (const float*)d_in[0];
    const float* W_emb = (const float*)d_in[1];
    const float* b_emb = (const float*)d_in[2];
    const float* Wi_a  = (const float*)d_in[3];
    const float* Wh_a  = (const float*)d_in[4];
    const float* bi_a  = (const float*)d_in[5];
    const float* bh_a  = (const float*)d_in[6];
    const float* Wi_b  = (const float*)d_in[7];
    const float* Wh_b  = (const float*)d_in[8];
    const float* bi_b  = (const float*)d_in[9];
    const float* bh_b  = (const float*)d_in[10];
    const float* Wa    = (const float*)d_in[11];
    const float* ba    = (const float*)d_in[12];
    const float* Wb    = (const float*)d_in[13];
    const float* bb    = (const float*)d_in[14];
    const float* Wo    = (const float*)d_in[15];
    const float* bo    = (const float*)d_in[16];
    float* out = (float*)d_out;

    int nq = out_size / (64 * 65);

    static int smem_set = 0;
    if (!smem_set) {
        cudaFuncSetAttribute(retain_main,
                             cudaFuncAttributeMaxDynamicSharedMemorySize, SMEM_TOTAL);
        smem_set = 1;
    }

    prep_transpose<<<256, 256>>>(x, Wh_a, Wh_b, Wi_a, Wi_b, Wb, W_emb, Wo);
    emb_kernel<<<Tn * Bn, 128>>>(x, b_emb);
    gi_kernel<<<Tn * Bn, 256>>>(bi_a, bi_b);
    retain_main<<<128, 256, SMEM_TOTAL>>>(bh_a, bh_b, Wa, ba, bb, Wo, bo, nq, out);
}

// round 16
// speedup vs baseline: 1.0918x; 1.0290x over previous
#include <cuda_runtime.h>
#include <cstdint>

#define Bn 64
#define Tn 64
#define Dn 64
#define Pn 63
typedef unsigned long long ull;

// ---------------- device scratch ----------------
__device__ __align__(16) float g_emb[Tn * Bn * 128];         // [t][b][e]
__device__ __align__(16) ull   g_embP[Tn * 32 * 128];        // [t][rpg][e]
__device__ __align__(16) ull   g_giP[64 * 2 * 32 * 3 * 128]; // [t][gru][rpg][gate][k]
__device__ __align__(16) ull   g_xP[64 * 32 * 64];           // [j][bp][d]
__device__ __align__(16) float g_WiaT[128 * 384];            // [e][u]
__device__ __align__(16) float g_WibT[128 * 384];
// combined per-warp tiles: [w 8][tile 8][ Wh: li16 x 96 | Wb: li16 x 32 ] = 2048 floats (8KB)
__device__ __align__(16) float g_WC[8 * 8 * 2048];
__device__ __align__(16) float g_WembT[64 * 128];            // [d][e]
__device__ __align__(16) float g_WoWemb[128 * 64];           // [e][d]

// ---------------- f32x2 helpers ----------------
__device__ __forceinline__ ull pack2(float x, float y) {
    ull r; asm("mov.b64 %0, {%1,%2};" : "=l"(r) : "f"(x), "f"(y)); return r;
}
__device__ __forceinline__ float2 unpack2(ull v) {
    float2 r; asm("mov.b64 {%0,%1}, %2;" : "=f"(r.x), "=f"(r.y) : "l"(v)); return r;
}
__device__ __forceinline__ ull fma2(ull a, ull b, ull c) {
    ull d; asm("fma.rn.f32x2 %0, %1, %2, %3;" : "=l"(d) : "l"(a), "l"(b), "l"(c)); return d;
}
__device__ __forceinline__ ull mul2(ull a, ull b) {
    ull d; asm("mul.rn.f32x2 %0, %1, %2;" : "=l"(d) : "l"(a), "l"(b)); return d;
}
__device__ __forceinline__ ull add2(ull a, ull b) {
    ull d; asm("add.rn.f32x2 %0, %1, %2;" : "=l"(d) : "l"(a), "l"(b)); return d;
}
__device__ __forceinline__ float sigmoidf_(float v) {
    return __fdividef(1.f, 1.f + __expf(-v));
}
__device__ __forceinline__ float tanhfast(float v) {
    float e = __expf(2.f * v);
    return 1.f - __fdividef(2.f, e + 1.f);
}
__device__ __forceinline__ float gru_step(float ir, float iz, float in_,
                                          float hr, float hz, float hn, float h) {
    float r = sigmoidf_(ir + hr);
    float z = sigmoidf_(iz + hz);
    float n = tanhfast(in_ + r * hn);
    return n + z * (h - n);
}

// ---------------- cp.async helpers ----------------
__device__ __forceinline__ void cp16(uint32_t dst, const void* src) {
    asm volatile("cp.async.cg.shared.global [%0], [%1], 16;\n" :: "r"(dst), "l"(src));
}
__device__ __forceinline__ void cp_commit() {
    asm volatile("cp.async.commit_group;\n" ::: "memory");
}
__device__ __forceinline__ void cp_wait1() {
    asm volatile("cp.async.wait_group 1;\n" ::: "memory");
}
__device__ __forceinline__ void cp_wait0() {
    asm volatile("cp.async.wait_group 0;\n" ::: "memory");
}

// ---------------- prep ----------------
__global__ void prep_transpose(const float* __restrict__ x,
                               const float* __restrict__ Wh_a,
                               const float* __restrict__ Wh_b,
                               const float* __restrict__ Wi_a,
                               const float* __restrict__ Wi_b,
                               const float* __restrict__ Wb,
                               const float* __restrict__ W_emb,
                               const float* __restrict__ Wo) {
    int idx = blockIdx.x * blockDim.x + threadIdx.x;
    int stride = gridDim.x * blockDim.x;
    for (int n = idx; n < 128 * 384; n += stride) {
        int u = n % 384, i = n / 384;
        g_WiaT[n] = Wi_a[u * 128 + i];
        g_WibT[n] = Wi_b[u * 128 + i];
    }
    for (int n = idx; n < 8 * 128 * 32; n += stride) {
        int w = n >> 12;
        int rem = n & 4095;
        int i = rem >> 5, kk = rem & 31;
        int gru = w >> 2, band = w & 3;
        int kq = band * 32 + kk;
        const float* Wh = gru ? Wh_b : Wh_a;
        float wr = Wh[kq * 128 + i];
        float wz = Wh[(128 + kq) * 128 + i];
        float wn = Wh[(256 + kq) * 128 + i];
        int tl = i >> 4, li = i & 15;
        int bas = (w * 8 + tl) * 2048 + li * 96;
        g_WC[bas + 2 * kk]     = wr;
        g_WC[bas + 2 * kk + 1] = wz;
        g_WC[bas + 64 + kk]    = wn;
    }
    for (int n = idx; n < 8 * 128 * 32; n += stride) {
        int w = n >> 12;
        int rem = n & 4095;
        int i = rem >> 5, kk = rem & 31;
        int band = w & 3;
        int tl = i >> 4, li = i & 15;
        g_WC[(w * 8 + tl) * 2048 + 1536 + li * 32 + kk] =
            Wb[(band * 32 + kk) * 128 + i];
    }
    for (int n = idx; n < 64 * 128; n += stride) {
        int e = n % 128, d = n / 128;
        g_WembT[n] = W_emb[e * 64 + d];
    }
    for (int n = idx; n < 128 * 64; n += stride) {
        int d = n % 64, e = n / 64;
        g_WoWemb[n] = Wo[e] * W_emb[e * 64 + d];
    }
    for (int n = idx; n < 64 * 32 * 64; n += stride) {
        int j = n >> 11;
        int bp = (n >> 6) & 31;
        int d = n & 63;
        float x0 = x[((size_t)(2 * bp) * Tn + j) * Dn + d];
        float x1 = x[((size_t)(2 * bp + 1) * Tn + j) * Dn + d];
        g_xP[n] = pack2(x0, x1);
    }
}

// ---------------- emb ----------------
__global__ void emb_kernel(const float* __restrict__ x, const float* __restrict__ b_emb) {
    __shared__ float xs[64];
    int tb = blockIdx.x;
    int t_ = tb >> 6, b = tb & 63;
    int e = threadIdx.x;
    if (e < 64) xs[e] = x[((size_t)b * Tn + t_) * Dn + e];
    __syncthreads();
    float acc = 0.f;
#pragma unroll 8
    for (int d = 0; d < 64; ++d) acc = fmaf(g_WembT[d * 128 + e], xs[d], acc);
    g_emb[(size_t)tb * 128 + e] = acc + b_emb[e];
}

// ---------------- gi (packed) + emb packing ----------------
__global__ void gi_kernel(const float* __restrict__ bi_a, const float* __restrict__ bi_b) {
    __shared__ float es[128];
    int tb = blockIdx.x;
    int t_ = tb >> 6, b = tb & 63;
    int t = threadIdx.x;
    if (t < 128) es[t] = g_emb[(size_t)tb * 128 + t];
    __syncthreads();
    float* gf = (float*)g_giP;
    for (int u = t; u < 768; u += 256) {
        const float* WT;
        const float* bi;
        int gru, uu;
        if (u < 384) { WT = g_WiaT; bi = bi_a; gru = 0; uu = u; }
        else         { WT = g_WibT; bi = bi_b; gru = 1; uu = u - 384; }
        float acc = 0.f;
#pragma unroll 8
        for (int e = 0; e < 128; ++e) acc = fmaf(WT[e * 384 + uu], es[e], acc);
        int gate = uu >> 7, k = uu & 127;
        size_t ullIdx = (((size_t)(t_ * 2 + gru) * 32 + (b >> 1)) * 3 + gate) * 128 + k;
        gf[ullIdx * 2 + (b & 1)] = acc + bi[uu];
    }
    if ((b & 1) == 0 && t < 128) {
        g_embP[((size_t)t_ * 32 + (b >> 1)) * 128 + t] =
            pack2(g_emb[(size_t)tb * 128 + t], g_emb[(size_t)(tb + 1) * 128 + t]);
    }
}

// ---------------- main persistent kernel ----------------
// 256 threads, 8 warps. Fused gh(s+1)+beta(s)+e_chain(s-1) loop; epilogue
// pipelined one step; double-buffered betaP/preA; ONE barrier per step.
#define RING_OFF   0                  // 8 warps x 2 slots x 8192 = 131072
#define SHH_OFF    131072             // ull [2][2][128][8] = 32768
#define BETA_OFF   163840             // ull [2][8][128] = 16384
#define WOW_OFF    180224             // float [128][64] = 32768
#define SCAL_OFF   212992             // preA[2][16], l[16], Wa[128]
#define SMEM_TOTAL 214016

__global__ __launch_bounds__(256, 1) void retain_main(
    const float* __restrict__ bh_a, const float* __restrict__ bh_b,
    const float* __restrict__ Wa, const float* __restrict__ ba,
    const float* __restrict__ bb, const float* __restrict__ Wo,
    const float* __restrict__ bo, int nq, float* __restrict__ out) {

    extern __shared__ char dsm[];
    float* smw = (float*)dsm;
    ull (*sh_h)[2][128][8]    = (ull (*)[2][128][8])(dsm + SHH_OFF);
    ull (*sh_betaP)[8][128]   = (ull (*)[8][128])(dsm + BETA_OFF);
    float* sWo                = (float*)(dsm + WOW_OFF);
    float* sh_preA  = (float*)(dsm + SCAL_OFF);    // [2][16]
    float* sh_l     = sh_preA + 32;                // [16]
    float* sh_Wa    = sh_preA + 48;                // [128]

    const int t = threadIdx.x;
    const int pb = blockIdx.x >> 2;
    const int chunkI = blockIdx.x & 3;
    const int b0 = chunkI * 16;

    const int w = t >> 5;
    const int lane = t & 31;
    const int gru = t >> 7;
    const int k = t & 127;
    const int kk = lane;
    const int q = t >> 6;

    const float* bh = gru ? bh_b : bh_a;
    const float bhr = bh[k], bhz = bh[128 + k], bhn = bh[256 + k];
    const float ba0 = ba[0], bbk = bb[k];
    const int base = Pn - nq;

    for (int n = t; n < 8192; n += 256) sWo[n] = g_WoWemb[n];
    if (t < 128) sh_Wa[t] = Wa[t];

    const bool seg2 = (pb < 31) && (pb >= base);
    const int totalSteps = (63 - pb) + (seg2 ? pb + 1 : 0);
    const int totalTiles = 8 * totalSteps;

    uint32_t ringB = (uint32_t)__cvta_generic_to_shared(dsm) + (uint32_t)(w * 16384);
    int issIdx = 0, issM = 0, issSlot = 0, consSlot = 0;

#define ISSUE_ONE() do {                                                        \
        if (issIdx < totalTiles) {                                              \
            const char* _src = (const char*)g_WC + ((size_t)(w * 8 + issM)) * 8192; \
            uint32_t _d = ringB + (uint32_t)(issSlot * 8192);                   \
            for (int _o = lane * 16; _o < 8192; _o += 512) cp16(_d + _o, _src + _o); \
            cp_commit();                                                        \
            ++issIdx; if (++issM == 8) issM = 0; issSlot ^= 1;                  \
        }                                                                       \
    } while (0)

#define WAITC() do {                                                            \
        if (issIdx < totalTiles) cp_wait1(); else cp_wait0();                   \
        __syncwarp();                                                           \
    } while (0)

    ISSUE_ONE();
    ISSUE_ONE();

    ull aR[8], aZ[8], aN[8];   // gh accumulators, pipelined across steps
    ull gbuf[24];              // gi for the current step

    for (int seg = 0; seg < 2; ++seg) {
        const int p = seg ? pb : 62 - pb;
        if (seg && !seg2) break;

        for (int n = t; n < 2 * 128 * 8; n += 256)
            ((ull*)sh_h[0])[n] = 0ull;
        // zero both betaP buffers (s=0 consumes buf1 with weight 0 -> must be finite)
        for (int n = t; n < 2 * 8 * 128; n += 256)
            ((ull*)sh_betaP)[n] = 0ull;
        if (t < 16) sh_preA[16 + t] = -1e30f;   // buf1: exp -> 0
        ull cacc[4] = {0ull, 0ull, 0ull, 0ull};
        ull gacc[2] = {0ull, 0ull};
        ull lacc0 = 0ull, lacc1 = 0ull;
#pragma unroll
        for (int r = 0; r < 8; ++r) { aR[r] = 0ull; aZ[r] = 0ull; aN[r] = 0ull; }
        // prefetch gi for step 0 (j = p)
        {
            const ull* gb = g_giP + (((size_t)(p * 2 + gru) * 32 + (b0 >> 1)) * 3) * 128 + k;
#pragma unroll
            for (int r = 0; r < 8; ++r) {
                gbuf[r * 3]     = gb[(size_t)r * 384];
                gbuf[r * 3 + 1] = gb[(size_t)r * 384 + 128];
                gbuf[r * 3 + 2] = gb[(size_t)r * 384 + 256];
            }
        }
        __syncthreads();

        for (int s = 0; s <= p; ++s) {
            const int j = p - s;
            const int cb = s & 1;
            const int pv = (s ^ 1) & 1;            // previous step's buffer
            const ull (*cur)[8]  = sh_h[cb][gru];
            ull (*nxtg)[8]       = sh_h[cb ^ 1][gru];
            const ull (*nxtA)[8] = sh_h[cb ^ 1][0];
            const ull (*nxtB)[8] = sh_h[cb ^ 1][1];

            // ---- GRU(s): h(s+1) from gh in aR (own data only) ----
            {
#pragma unroll
                for (int r = 0; r < 8; ++r) {
                    float2 gr = unpack2(gbuf[r * 3]);
                    float2 gz = unpack2(gbuf[r * 3 + 1]);
                    float2 gn = unpack2(gbuf[r * 3 + 2]);
                    float2 hr = unpack2(aR[r]);
                    float2 hz = unpack2(aZ[r]);
                    float2 hn = unpack2(aN[r]);
                    float2 ho = unpack2(cur[k][r]);
                    float hx = gru_step(gr.x, gz.x, gn.x,
                                        hr.x + bhr, hz.x + bhz, hn.x + bhn, ho.x);
                    float hy = gru_step(gr.y, gz.y, gn.y,
                                        hr.y + bhr, hz.y + bhz, hn.y + bhn, ho.y);
                    nxtg[k][r] = pack2(hx, hy);
                }
            }
            __syncthreads();   // BAR1: the ONLY barrier per step

            // ---- prefetch gi(s+1) + emb/x for step s-1 (latency covered by fused) ----
            {
                int jn = (j > 0) ? j - 1 : 0;
                const ull* gb = g_giP + (((size_t)(jn * 2 + gru) * 32 + (b0 >> 1)) * 3) * 128 + k;
#pragma unroll
                for (int r = 0; r < 8; ++r) {
                    gbuf[r * 3]     = gb[(size_t)r * 384];
                    gbuf[r * 3 + 1] = gb[(size_t)r * 384 + 128];
                    gbuf[r * 3 + 2] = gb[(size_t)r * 384 + 256];
                }
            }
            ull ebr[4], xr0, xr1;
            {
                const int jp = j + 1;    // timestep of step s-1 (s=0: weight 0, harmless)
                const ull* ebp = g_embP + ((size_t)jp * 32 + (b0 >> 1) + 4 * gru) * 128 + k;
#pragma unroll
                for (int c = 0; c < 4; ++c) ebr[c] = ebp[(size_t)c * 128];
                const ull* xb = g_xP + ((size_t)jp * 32 + (b0 >> 1) + q) * 64 + (t & 63);
                xr0 = xb[0];
                xr1 = xb[4 * 64];
            }

            // ---- preA(s) on the new h ----
            {
#pragma unroll
                for (int rr = 0; rr < 2; ++rr) {
                    int r = w + 8 * rr;
                    float part = 0.f;
#pragma unroll
                    for (int ii = 0; ii < 4; ++ii) {
                        int i = lane + 32 * ii;
                        float2 hv = unpack2(nxtA[i][r >> 1]);
                        part = fmaf(sh_Wa[i], (r & 1) ? hv.y : hv.x, part);
                    }
#pragma unroll
                    for (int o = 16; o; o >>= 1)
                        part += __shfl_xor_sync(0xffffffffu, part, o);
                    if (lane == 0) sh_preA[cb * 16 + r] = fmaf(0.5f, part, ba0);
                }
            }

            // ---- FUSED: gh(s+1) + beta(s) + e_chain(s-1) ----
#pragma unroll
            for (int r = 0; r < 8; ++r) { aR[r] = 0ull; aZ[r] = 0ull; aN[r] = 0ull; }
            ull bacc[4] = {0ull, 0ull, 0ull, 0ull};
            ull ea0 = 0ull, ea1 = 0ull;
            const ull* bpp0 = sh_betaP[pv][q];
            const ull* bpp1 = sh_betaP[pv][q + 4];
            const float* wcp = sWo + (t & 63);
#pragma unroll 1
            for (int tl = 0; tl < 8; ++tl) {
                WAITC();
                const float* wp = smw + w * 4096 + consSlot * 2048;
                consSlot ^= 1;
                const ull (*hrow)[8]  = (const ull (*)[8])&nxtg[tl * 16];
                const ull (*hrowB)[8] = &nxtB[tl * 16];
#pragma unroll
                for (int li = 0; li < 16; ++li) {
                    float2 rz = *(const float2*)(wp + li * 96 + 2 * kk);
                    float wnv = wp[li * 96 + 64 + kk];
                    float wbv = wp[1536 + li * 32 + kk];
                    ull wr2 = pack2(rz.x, rz.x), wz2 = pack2(rz.y, rz.y);
                    ull wn2 = pack2(wnv, wnv), wb2 = pack2(wbv, wbv);
                    const ulonglong2* hp = reinterpret_cast<const ulonglong2*>(hrow[li]);
                    ulonglong2 hA = hp[0], hB = hp[1], hC = hp[2], hD = hp[3];
                    const ulonglong2* hq =
                        reinterpret_cast<const ulonglong2*>(hrowB[li] + 4 * gru);
                    ulonglong2 b0v = hq[0], b1v = hq[1];
                    aR[0] = fma2(wr2, hA.x, aR[0]); aZ[0] = fma2(wz2, hA.x, aZ[0]); aN[0] = fma2(wn2, hA.x, aN[0]);
                    bacc[0] = fma2(wb2, b0v.x, bacc[0]);
                    aR[1] = fma2(wr2, hA.y, aR[1]); aZ[1] = fma2(wz2, hA.y, aZ[1]); aN[1] = fma2(wn2, hA.y, aN[1]);
                    bacc[1] = fma2(wb2, b0v.y, bacc[1]);
                    aR[2] = fma2(wr2, hB.x, aR[2]); aZ[2] = fma2(wz2, hB.x, aZ[2]); aN[2] = fma2(wn2, hB.x, aN[2]);
                    bacc[2] = fma2(wb2, b1v.x, bacc[2]);
                    aR[3] = fma2(wr2, hB.y, aR[3]); aZ[3] = fma2(wz2, hB.y, aZ[3]); aN[3] = fma2(wn2, hB.y, aN[3]);
                    bacc[3] = fma2(wb2, b1v.y, bacc[3]);
                    aR[4] = fma2(wr2, hC.x, aR[4]); aZ[4] = fma2(wz2, hC.x, aZ[4]); aN[4] = fma2(wn2, hC.x, aN[4]);
                    aR[5] = fma2(wr2, hC.y, aR[5]); aZ[5] = fma2(wz2, hC.y, aZ[5]); aN[5] = fma2(wn2, hC.y, aN[5]);
                    aR[6] = fma2(wr2, hD.x, aR[6]); aZ[6] = fma2(wz2, hD.x, aZ[6]); aN[6] = fma2(wn2, hD.x, aN[6]);
                    aR[7] = fma2(wr2, hD.y, aR[7]); aZ[7] = fma2(wz2, hD.y, aZ[7]); aN[7] = fma2(wn2, hD.y, aN[7]);
                }
                // interleaved e_chain(s-1), 16 e per tile
#pragma unroll
                for (int ee = 0; ee < 16; ++ee) {
                    int e = tl * 16 + ee;
                    float wc = wcp[e * 64];
                    ull wc2 = pack2(wc, wc);
                    ea0 = fma2(wc2, bpp0[e], ea0);
                    ea1 = fma2(wc2, bpp1[e], ea1);
                }
                ISSUE_ONE();
            }

            // ---- accum(s-1), unnormalized ----
            {
                const float* pap = sh_preA + pv * 16;
                ull wg0 = pack2(__expf(pap[2 * q]), __expf(pap[2 * q + 1]));
                ull wg1 = pack2(__expf(pap[2 * q + 8]), __expf(pap[2 * q + 9]));
                lacc0 = add2(lacc0, wg0);
                lacc1 = add2(lacc1, wg1);
#pragma unroll
                for (int c = 0; c < 4; ++c) {
                    int rp = 4 * gru + c;
                    ull wcv = pack2(__expf(pap[2 * rp]), __expf(pap[2 * rp + 1]));
                    ull btv = sh_betaP[pv][rp][k];
                    cacc[c] = fma2(mul2(wcv, btv), ebr[c], cacc[c]);
                }
                gacc[0] = fma2(mul2(wg0, ea0), xr0, gacc[0]);
                gacc[1] = fma2(mul2(wg1, ea1), xr1, gacc[1]);
            }

            // ---- beta(s) tanh -> sh_betaP[cb] ----
#pragma unroll
            for (int c = 0; c < 4; ++c) {
                float2 v = unpack2(bacc[c]);
                sh_betaP[cb][4 * gru + c][k] =
                    pack2(tanhfast(fmaf(0.5f, v.x, bbk)),
                          tanhfast(fmaf(0.5f, v.y, bbk)));
            }
            // no BAR here: all cross-thread reads of beta(s)/preA(s) happen after
            // BAR1(s+1); sh_h ping-pong is same-thread.
        } // steps

        // ---- epilogue: drain attention step p ----
        __syncthreads();   // fence betaP(p)/preA(p)
        {
            const int pvp = p & 1;
            ull ebr[4], xr0, xr1;
            const ull* ebp = g_embP + ((size_t)(b0 >> 1) + 4 * gru) * 128 + k;  // j = 0
#pragma unroll
            for (int c = 0; c < 4; ++c) ebr[c] = ebp[(size_t)c * 128];
            const ull* xb = g_xP + ((size_t)(b0 >> 1) + q) * 64 + (t & 63);
            xr0 = xb[0];
            xr1 = xb[4 * 64];

            ull ea0 = 0ull, ea1 = 0ull;
            const ull* bpp0 = sh_betaP[pvp][q];
            const ull* bpp1 = sh_betaP[pvp][q + 4];
            const float* wcp = sWo + (t & 63);
#pragma unroll 4
            for (int e = 0; e < 128; ++e) {
                float wc = wcp[e * 64];
                ull wc2 = pack2(wc, wc);
                ea0 = fma2(wc2, bpp0[e], ea0);
                ea1 = fma2(wc2, bpp1[e], ea1);
            }
            const float* pap = sh_preA + pvp * 16;
            ull wg0 = pack2(__expf(pap[2 * q]), __expf(pap[2 * q + 1]));
            ull wg1 = pack2(__expf(pap[2 * q + 8]), __expf(pap[2 * q + 9]));
            lacc0 = add2(lacc0, wg0);
            lacc1 = add2(lacc1, wg1);
#pragma unroll
            for (int c = 0; c < 4; ++c) {
                int rp = 4 * gru + c;
                ull wcv = pack2(__expf(pap[2 * rp]), __expf(pap[2 * rp + 1]));
                ull btv = sh_betaP[pvp][rp][k];
                cacc[c] = fma2(mul2(wcv, btv), ebr[c], cacc[c]);
            }
            gacc[0] = fma2(mul2(wg0, ea0), xr0, gacc[0]);
            gacc[1] = fma2(mul2(wg1, ea1), xr1, gacc[1]);
        }
        __syncthreads();   // all epilogue reads of betaP done before staging overwrite

        // ---- finalize ----
        if (p >= base) {
            const int qi = p - base;
#pragma unroll
            for (int c = 0; c < 4; ++c) sh_betaP[0][4 * gru + c][k] = cacc[c];
            if ((t & 63) == 0) {
                float2 l0 = unpack2(lacc0), l1 = unpack2(lacc1);
                sh_l[2 * q] = l0.x; sh_l[2 * q + 1] = l0.y;
                sh_l[2 * q + 8] = l1.x; sh_l[2 * q + 9] = l1.y;
            }
            __syncthreads();

            if (t < 16) {
                float sum = 0.f;
                const ull* Crow = sh_betaP[0][t >> 1];
                const bool hi = (t & 1);
#pragma unroll 8
                for (int e = 0; e < 128; ++e) {
                    float2 v = unpack2(Crow[e]);
                    sum = fmaf(Wo[e], hi ? v.y : v.x, sum);
                }
                out[(size_t)(b0 + t) * nq + qi] = __fdividef(sum, sh_l[t]) + bo[0];
            }
            {
                float inv = __fdividef(1.f, (float)(p + 1));
                size_t wbase = (size_t)64 * nq;
                float2 lg0 = unpack2(lacc0), lg1 = unpack2(lacc1);
#pragma unroll
                for (int cc = 0; cc < 2; ++cc) {
                    int rp = q + 4 * cc;
                    float2 gv = unpack2(gacc[cc]);
                    float lx = cc ? lg1.x : lg0.x;
                    float ly = cc ? lg1.y : lg0.y;
                    out[wbase + ((size_t)(b0 + 2 * rp) * nq + qi) * 64 + (t & 63)] =
                        __fdividef(gv.x, lx) * inv;
                    out[wbase + ((size_t)(b0 + 2 * rp + 1) * nq + qi) * 64 + (t & 63)] =
                        __fdividef(gv.y, ly) * inv;
                }
            }
        }
        __syncthreads();
    } // segments
#undef WAITC
#undef ISSUE_ONE
}

// ---------------- launch ----------------
extern "C" void kernel_launch(void* const* d_in, const int* in_sizes, int n_in,
                              void* d_out, int out_size) {
    const float* x     = (const float*)d_in[0];
    const float* W_emb = (const float*)d_in[1];
    const float* b_emb = (const float*)d_in[2];
    const float* Wi_a  = (const float*)d_in[3];
    const float* Wh_a  = (const float*)d_in[4];
    const float* bi_a  = (const float*)d_in[5];
    const float* bh_a  = (const float*)d_in[6];
    const float* Wi_b  = (const float*)d_in[7];
    const float* Wh_b  = (const float*)d_in[8];
    const float* bi_b  = (const float*)d_in[9];
    const float* bh_b  = (const float*)d_in[10];
    const float* Wa    = (const float*)d_in[11];
    const float* ba    = (const float*)d_in[12];
    const float* Wb    = (const float*)d_in[13];
    const float* bb    = (const float*)d_in[14];
    const float* Wo    = (const float*)d_in[15];
    const float* bo    = (const float*)d_in[16];
    float* out = (float*)d_out;

    int nq = out_size / (64 * 65);

    static int smem_set = 0;
    if (!smem_set) {
        cudaFuncSetAttribute(retain_main,
                             cudaFuncAttributeMaxDynamicSharedMemorySize, SMEM_TOTAL);
        smem_set = 1;
    }

    prep_transpose<<<256, 256>>>(x, Wh_a, Wh_b, Wi_a, Wi_b, Wb, W_emb, Wo);
    emb_kernel<<<Tn * Bn, 128>>>(x, b_emb);
    gi_kernel<<<Tn * Bn, 256>>>(bi_a, bi_b);
    retain_main<<<128, 256, SMEM_TOTAL>>>(bh_a, bh_b, Wa, ba, bb, Wo, bo, nq, out);
}